// round 1
// baseline (speedup 1.0000x reference)
#include <cuda_runtime.h>
#include <math.h>

// Problem constants
#define BB   2
#define SS   2048
#define DM   1024
#define HH   16
#define DK   64
#define NQKV 3072          // 3*DM
#define MTOT 4096          // BB*SS
#define EPSG 0.1f

// Scratch: q,k,v,attn_out in [B,H,S,DK] layout. 4 x 16 MiB.
__device__ float g_q [BB*HH*SS*DK];
__device__ float g_k [BB*HH*SS*DK];
__device__ float g_v [BB*HH*SS*DK];
__device__ float g_ao[BB*HH*SS*DK];

// ---------------------------------------------------------------------------
// Kernel 1: qkv = x @ qkv_w^T + qkv_b, fused clamp + scatter into g_q/g_k/g_v
// SGEMM: M=4096, N=3072, K=1024. Block tile 128x128, ktile 16, 256 threads,
// 8x8 per thread.
// ---------------------------------------------------------------------------
__global__ __launch_bounds__(256) void qkv_gemm_kernel(
    const float* __restrict__ x,      // [4096,1024]
    const float* __restrict__ w,      // [3072,1024]
    const float* __restrict__ bias,   // [3072]
    const float* __restrict__ akmin,  // [B,H,1,DK]
    const float* __restrict__ akmax,
    const float* __restrict__ avmin,
    const float* __restrict__ avmax)
{
    __shared__ float As[16 * 132];
    __shared__ float Bs[16 * 132];

    const int tid = threadIdx.x;
    const int tx  = tid & 15;     // 0..15 -> n micro
    const int ty  = tid >> 4;     // 0..15 -> m micro
    const int m0  = blockIdx.y * 128;
    const int n0  = blockIdx.x * 128;

    float acc[8][8];
    #pragma unroll
    for (int i = 0; i < 8; i++)
        #pragma unroll
        for (int j = 0; j < 8; j++) acc[i][j] = 0.f;

    for (int k0 = 0; k0 < DM; k0 += 16) {
        // Load A tile (128 rows x 16 k) as 512 float4, 2 per thread
        #pragma unroll
        for (int l = 0; l < 2; l++) {
            int f   = tid * 2 + l;
            int row = f >> 2;
            int c4  = f & 3;
            float4 v = *(const float4*)(x + (size_t)(m0 + row) * DM + k0 + c4 * 4);
            As[(c4 * 4 + 0) * 132 + row] = v.x;
            As[(c4 * 4 + 1) * 132 + row] = v.y;
            As[(c4 * 4 + 2) * 132 + row] = v.z;
            As[(c4 * 4 + 3) * 132 + row] = v.w;
        }
        // Load B tile (128 n-rows x 16 k)
        #pragma unroll
        for (int l = 0; l < 2; l++) {
            int f   = tid * 2 + l;
            int row = f >> 2;
            int c4  = f & 3;
            float4 v = *(const float4*)(w + (size_t)(n0 + row) * DM + k0 + c4 * 4);
            Bs[(c4 * 4 + 0) * 132 + row] = v.x;
            Bs[(c4 * 4 + 1) * 132 + row] = v.y;
            Bs[(c4 * 4 + 2) * 132 + row] = v.z;
            Bs[(c4 * 4 + 3) * 132 + row] = v.w;
        }
        __syncthreads();

        #pragma unroll
        for (int kt = 0; kt < 16; kt++) {
            float a[8], b[8];
            #pragma unroll
            for (int i = 0; i < 8; i++) a[i] = As[kt * 132 + ty * 8 + i];
            #pragma unroll
            for (int j = 0; j < 8; j++) b[j] = Bs[kt * 132 + tx * 8 + j];
            #pragma unroll
            for (int i = 0; i < 8; i++)
                #pragma unroll
                for (int j = 0; j < 8; j++) acc[i][j] += a[i] * b[j];
        }
        __syncthreads();
    }

    // Epilogue: bias, clamp (k,v), scatter to [B,H,S,DK]
    #pragma unroll
    for (int i = 0; i < 8; i++) {
        int m = m0 + ty * 8 + i;
        int b = m >> 11;           // /2048
        int s = m & 2047;
        #pragma unroll
        for (int j = 0; j < 8; j++) {
            int n   = n0 + tx * 8 + j;
            float v = acc[i][j] + bias[n];
            int t   = n >> 10;          // 0=q,1=k,2=v
            int rem = n & 1023;
            int h   = rem >> 6;
            int ch  = rem & 63;
            size_t didx = ((size_t)(b * HH + h) * SS + s) * DK + ch;
            if (t == 0) {
                g_q[didx] = v;
            } else {
                int aidx = (b * HH + h) * DK + ch;
                const float* amin = (t == 1) ? akmin : avmin;
                const float* amax = (t == 1) ? akmax : avmax;
                float lo = fmaxf(v - EPSG, amin[aidx]);
                float hi = fminf(v + EPSG, amax[aidx]);
                lo = fminf(lo, hi);
                float cl = fmaxf(lo, fminf(v, hi));
                if (t == 1) g_k[didx] = cl; else g_v[didx] = cl;
            }
        }
    }
}

// ---------------------------------------------------------------------------
// Kernel 2: flash attention per (b,h). BM=64 queries/block, BN=32 keys/tile.
// 256 threads: tx (0..15) spans key/dk cols, ty (0..15) spans 4-query rows.
// Static shared < 48 KB.
// ---------------------------------------------------------------------------
__global__ __launch_bounds__(256) void attn_kernel()
{
    __shared__ float Qt[64 * 68];   // d-major: Qt[d][q]
    __shared__ float Kt[64 * 36];   // d-major: Kt[d][kj], kj 0..31
    __shared__ float Vs[32 * 68];   // key-major: Vs[kj][d]
    __shared__ float Ps[64 * 36];   // Ps[q][kj]

    const int tid = threadIdx.x;
    const int tx  = tid & 15;
    const int ty  = tid >> 4;
    const int ty4 = ty * 4;
    const int tx2 = tx * 2;
    const int tx4 = tx * 4;

    const int bh = blockIdx.y;           // 0..31
    const int q0 = blockIdx.x * 64;

    const float* qbase = g_q + (size_t)bh * SS * DK + (size_t)q0 * DK;
    const float* kbase = g_k + (size_t)bh * SS * DK;
    const float* vbase = g_v + (size_t)bh * SS * DK;

    // Load Q tile 64x64 (1024 float4), transposed into Qt[d][q]
    #pragma unroll
    for (int l = 0; l < 4; l++) {
        int f   = l * 256 + tid;
        int row = f >> 4;       // 0..63 query
        int c4  = f & 15;       // d/4
        float4 v = *(const float4*)(qbase + row * DK + c4 * 4);
        Qt[(c4 * 4 + 0) * 68 + row] = v.x;
        Qt[(c4 * 4 + 1) * 68 + row] = v.y;
        Qt[(c4 * 4 + 2) * 68 + row] = v.z;
        Qt[(c4 * 4 + 3) * 68 + row] = v.w;
    }

    float m_run[4], l_run[4], o[4][4];
    #pragma unroll
    for (int r = 0; r < 4; r++) {
        m_run[r] = -1e30f;
        l_run[r] = 0.f;
        #pragma unroll
        for (int c = 0; c < 4; c++) o[r][c] = 0.f;
    }

    for (int j0 = 0; j0 < SS; j0 += 32) {
        // Load K tile (32x64) transposed, V tile direct. 512 float4 each.
        #pragma unroll
        for (int l = 0; l < 2; l++) {
            int f   = l * 256 + tid;
            int row = f >> 4;       // 0..31 key
            int c4  = f & 15;
            float4 kv = *(const float4*)(kbase + (size_t)(j0 + row) * DK + c4 * 4);
            Kt[(c4 * 4 + 0) * 36 + row] = kv.x;
            Kt[(c4 * 4 + 1) * 36 + row] = kv.y;
            Kt[(c4 * 4 + 2) * 36 + row] = kv.z;
            Kt[(c4 * 4 + 3) * 36 + row] = kv.w;
            float4 vv = *(const float4*)(vbase + (size_t)(j0 + row) * DK + c4 * 4);
            *(float4*)&Vs[row * 68 + c4 * 4] = vv;
        }
        __syncthreads();

        // S = Q K^T : s[4 rows][2 key cols]
        float s[4][2];
        #pragma unroll
        for (int r = 0; r < 4; r++) { s[r][0] = 0.f; s[r][1] = 0.f; }

        #pragma unroll 8
        for (int d = 0; d < 64; d++) {
            float4 qa = *(const float4*)&Qt[d * 68 + ty4];
            float2 kb = *(const float2*)&Kt[d * 36 + tx2];
            s[0][0] += qa.x * kb.x;  s[0][1] += qa.x * kb.y;
            s[1][0] += qa.y * kb.x;  s[1][1] += qa.y * kb.y;
            s[2][0] += qa.z * kb.x;  s[2][1] += qa.z * kb.y;
            s[3][0] += qa.w * kb.x;  s[3][1] += qa.w * kb.y;
        }

        // Online softmax per query row (row spread across 16 tx lanes)
        #pragma unroll
        for (int r = 0; r < 4; r++) {
            float s0 = s[r][0] * 0.125f;
            float s1 = s[r][1] * 0.125f;
            float tm = fmaxf(s0, s1);
            #pragma unroll
            for (int off = 8; off >= 1; off >>= 1)
                tm = fmaxf(tm, __shfl_xor_sync(0xffffffffu, tm, off, 16));
            float mn   = fmaxf(m_run[r], tm);
            float corr = __expf(m_run[r] - mn);
            float p0   = __expf(s0 - mn);
            float p1   = __expf(s1 - mn);
            float rs   = p0 + p1;
            #pragma unroll
            for (int off = 8; off >= 1; off >>= 1)
                rs += __shfl_xor_sync(0xffffffffu, rs, off, 16);
            l_run[r] = l_run[r] * corr + rs;
            m_run[r] = mn;
            o[r][0] *= corr; o[r][1] *= corr; o[r][2] *= corr; o[r][3] *= corr;
            Ps[(ty4 + r) * 36 + tx2 + 0] = p0;
            Ps[(ty4 + r) * 36 + tx2 + 1] = p1;
        }
        __syncthreads();

        // O += P V
        #pragma unroll 8
        for (int kc = 0; kc < 32; kc++) {
            float4 v4 = *(const float4*)&Vs[kc * 68 + tx4];
            #pragma unroll
            for (int r = 0; r < 4; r++) {
                float p = Ps[(ty4 + r) * 36 + kc];
                o[r][0] += p * v4.x;
                o[r][1] += p * v4.y;
                o[r][2] += p * v4.z;
                o[r][3] += p * v4.w;
            }
        }
        __syncthreads();
    }

    float* obase = g_ao + (size_t)bh * SS * DK + (size_t)q0 * DK;
    #pragma unroll
    for (int r = 0; r < 4; r++) {
        float inv = 1.f / l_run[r];
        #pragma unroll
        for (int c = 0; c < 4; c++)
            obase[(ty4 + r) * DK + tx4 + c] = o[r][c] * inv;
    }
}

// ---------------------------------------------------------------------------
// Kernel 3: out = attn @ out_w^T + out_b. M=4096, N=1024, K=1024.
// A gathered from g_ao [B,H,S,DK] layout.
// ---------------------------------------------------------------------------
__global__ __launch_bounds__(256) void out_gemm_kernel(
    const float* __restrict__ w,     // [1024,1024]
    const float* __restrict__ bias,  // [1024]
    float* __restrict__ out)         // [4096,1024]
{
    __shared__ float As[16 * 132];
    __shared__ float Bs[16 * 132];

    const int tid = threadIdx.x;
    const int tx  = tid & 15;
    const int ty  = tid >> 4;
    const int m0  = blockIdx.y * 128;
    const int n0  = blockIdx.x * 128;

    float acc[8][8];
    #pragma unroll
    for (int i = 0; i < 8; i++)
        #pragma unroll
        for (int j = 0; j < 8; j++) acc[i][j] = 0.f;

    for (int k0 = 0; k0 < DM; k0 += 16) {
        #pragma unroll
        for (int l = 0; l < 2; l++) {
            int f   = tid * 2 + l;
            int row = f >> 2;
            int c4  = f & 3;
            int m   = m0 + row;
            int b   = m >> 11;
            int s   = m & 2047;
            int kk  = k0 + c4 * 4;
            int h   = kk >> 6;
            int ch  = kk & 63;
            float4 v = *(const float4*)(g_ao + ((size_t)(b * HH + h) * SS + s) * DK + ch);
            As[(c4 * 4 + 0) * 132 + row] = v.x;
            As[(c4 * 4 + 1) * 132 + row] = v.y;
            As[(c4 * 4 + 2) * 132 + row] = v.z;
            As[(c4 * 4 + 3) * 132 + row] = v.w;
        }
        #pragma unroll
        for (int l = 0; l < 2; l++) {
            int f   = tid * 2 + l;
            int row = f >> 2;
            int c4  = f & 3;
            float4 v = *(const float4*)(w + (size_t)(n0 + row) * DM + k0 + c4 * 4);
            Bs[(c4 * 4 + 0) * 132 + row] = v.x;
            Bs[(c4 * 4 + 1) * 132 + row] = v.y;
            Bs[(c4 * 4 + 2) * 132 + row] = v.z;
            Bs[(c4 * 4 + 3) * 132 + row] = v.w;
        }
        __syncthreads();

        #pragma unroll
        for (int kt = 0; kt < 16; kt++) {
            float a[8], b[8];
            #pragma unroll
            for (int i = 0; i < 8; i++) a[i] = As[kt * 132 + ty * 8 + i];
            #pragma unroll
            for (int j = 0; j < 8; j++) b[j] = Bs[kt * 132 + tx * 8 + j];
            #pragma unroll
            for (int i = 0; i < 8; i++)
                #pragma unroll
                for (int j = 0; j < 8; j++) acc[i][j] += a[i] * b[j];
        }
        __syncthreads();
    }

    #pragma unroll
    for (int i = 0; i < 8; i++) {
        int m = m0 + ty * 8 + i;
        #pragma unroll
        for (int j = 0; j < 8; j++) {
            int n = n0 + tx * 8 + j;
            out[(size_t)m * DM + n] = acc[i][j] + bias[n];
        }
    }
}

// ---------------------------------------------------------------------------
extern "C" void kernel_launch(void* const* d_in, const int* in_sizes, int n_in,
                              void* d_out, int out_size)
{
    const float* x      = (const float*)d_in[0];
    const float* qkv_w  = (const float*)d_in[1];
    const float* qkv_b  = (const float*)d_in[2];
    const float* out_w  = (const float*)d_in[3];
    const float* out_b  = (const float*)d_in[4];
    const float* akmin  = (const float*)d_in[5];
    const float* akmax  = (const float*)d_in[6];
    const float* avmin  = (const float*)d_in[7];
    const float* avmax  = (const float*)d_in[8];
    float* out = (float*)d_out;

    qkv_gemm_kernel<<<dim3(NQKV / 128, MTOT / 128), 256>>>(
        x, qkv_w, qkv_b, akmin, akmax, avmin, avmax);

    attn_kernel<<<dim3(SS / 64, BB * HH), 256>>>();

    out_gemm_kernel<<<dim3(DM / 128, MTOT / 128), 256>>>(out_w, out_b, out);
}

// round 3
// speedup vs baseline: 1.2345x; 1.2345x over previous
#include <cuda_runtime.h>
#include <math.h>

// Problem constants
#define BB   2
#define SS   2048
#define DM   1024
#define HH   16
#define DK   64
#define NQKV 3072
#define MTOT 4096
#define EPSG 0.1f

// Scratch: q,k,v,attn_out in [B,H,S,DK] layout.
__device__ float g_q [BB*HH*SS*DK];
__device__ float g_k [BB*HH*SS*DK];
__device__ float g_v [BB*HH*SS*DK];
__device__ float g_ao[BB*HH*SS*DK];

// ---------------------------------------------------------------------------
// tf32 helpers
// ---------------------------------------------------------------------------
__device__ __forceinline__ void split_tf32(float a, unsigned &hi, unsigned &lo) {
    asm("cvt.rna.tf32.f32 %0, %1;" : "=r"(hi) : "f"(a));
    float l = a - __uint_as_float(hi);
    asm("cvt.rna.tf32.f32 %0, %1;" : "=r"(lo) : "f"(l));
}

__device__ __forceinline__ void mma8(float* d, const unsigned* a, const unsigned* b) {
    asm volatile(
        "mma.sync.aligned.m16n8k8.row.col.f32.tf32.tf32.f32 "
        "{%0,%1,%2,%3}, {%4,%5,%6,%7}, {%8,%9}, {%0,%1,%2,%3};"
        : "+f"(d[0]), "+f"(d[1]), "+f"(d[2]), "+f"(d[3])
        : "r"(a[0]), "r"(a[1]), "r"(a[2]), "r"(a[3]), "r"(b[0]), "r"(b[1]));
}

// C-fragment layout (cols 2c,2c+1) -> A-fragment layout (cols c, c+4), within
// each 4-lane group. Pure shuffles.
__device__ __forceinline__ void c2a(float p0, float p1, float p2, float p3,
                                    float &a0, float &a1, float &a2, float &a3,
                                    int lane) {
    int base = lane & ~3;
    int s0 = base + ((lane & 3) >> 1);
    int s1 = s0 + 2;
    int odd = lane & 1;
    float x00 = __shfl_sync(0xffffffffu, p0, s0);
    float x10 = __shfl_sync(0xffffffffu, p1, s0);
    float x20 = __shfl_sync(0xffffffffu, p2, s0);
    float x30 = __shfl_sync(0xffffffffu, p3, s0);
    float x01 = __shfl_sync(0xffffffffu, p0, s1);
    float x11 = __shfl_sync(0xffffffffu, p1, s1);
    float x21 = __shfl_sync(0xffffffffu, p2, s1);
    float x31 = __shfl_sync(0xffffffffu, p3, s1);
    a0 = odd ? x10 : x00;
    a1 = odd ? x30 : x20;
    a2 = odd ? x11 : x01;
    a3 = odd ? x31 : x21;
}

// ---------------------------------------------------------------------------
// Kernel 1: qkv = x @ qkv_w^T + qkv_b, fused clamp + scatter.
// M=4096, N=3072, K=1024. Block 128x128, ktile 32, 8 warps (2x4),
// warp tile 64x32, 3xTF32 mma.
// ---------------------------------------------------------------------------
__global__ __launch_bounds__(256, 1) void qkv_gemm_kernel(
    const float* __restrict__ x,      // [4096,1024]
    const float* __restrict__ w,      // [3072,1024]
    const float* __restrict__ bias,   // [3072]
    const float* __restrict__ akmin,
    const float* __restrict__ akmax,
    const float* __restrict__ avmin,
    const float* __restrict__ avmax)
{
    __shared__ float As[32 * 132];   // k-major [k][m]
    __shared__ float Bs[32 * 132];   // k-major [k][n]

    const int tid  = threadIdx.x;
    const int lane = tid & 31, warp = tid >> 5;
    const int g = lane >> 2, c = lane & 3;
    const int wm = warp >> 2, wn = warp & 3;
    const int m0 = blockIdx.y * 128, n0 = blockIdx.x * 128;

    float acc[4][4][4];
    #pragma unroll
    for (int mt = 0; mt < 4; mt++)
        #pragma unroll
        for (int nt = 0; nt < 4; nt++)
            #pragma unroll
            for (int i = 0; i < 4; i++) acc[mt][nt][i] = 0.f;

    for (int k0 = 0; k0 < DM; k0 += 32) {
        #pragma unroll
        for (int l = 0; l < 4; l++) {
            int f   = l * 256 + tid;
            int row = f >> 3;
            int c4  = f & 7;
            float4 v = *(const float4*)(x + (size_t)(m0 + row) * DM + k0 + c4 * 4);
            As[(c4 * 4 + 0) * 132 + row] = v.x;
            As[(c4 * 4 + 1) * 132 + row] = v.y;
            As[(c4 * 4 + 2) * 132 + row] = v.z;
            As[(c4 * 4 + 3) * 132 + row] = v.w;
            float4 u = *(const float4*)(w + (size_t)(n0 + row) * DM + k0 + c4 * 4);
            Bs[(c4 * 4 + 0) * 132 + row] = u.x;
            Bs[(c4 * 4 + 1) * 132 + row] = u.y;
            Bs[(c4 * 4 + 2) * 132 + row] = u.z;
            Bs[(c4 * 4 + 3) * 132 + row] = u.w;
        }
        __syncthreads();

        #pragma unroll
        for (int ks = 0; ks < 32; ks += 8) {
            unsigned ah[4][4], al[4][4], bh[4][2], bl[4][2];
            #pragma unroll
            for (int mt = 0; mt < 4; mt++) {
                int mb = wm * 64 + mt * 16 + g;
                split_tf32(As[(ks + c    ) * 132 + mb    ], ah[mt][0], al[mt][0]);
                split_tf32(As[(ks + c    ) * 132 + mb + 8], ah[mt][1], al[mt][1]);
                split_tf32(As[(ks + c + 4) * 132 + mb    ], ah[mt][2], al[mt][2]);
                split_tf32(As[(ks + c + 4) * 132 + mb + 8], ah[mt][3], al[mt][3]);
            }
            #pragma unroll
            for (int nt = 0; nt < 4; nt++) {
                int nb = wn * 32 + nt * 8 + g;
                split_tf32(Bs[(ks + c    ) * 132 + nb], bh[nt][0], bl[nt][0]);
                split_tf32(Bs[(ks + c + 4) * 132 + nb], bh[nt][1], bl[nt][1]);
            }
            #pragma unroll
            for (int mt = 0; mt < 4; mt++)
                #pragma unroll
                for (int nt = 0; nt < 4; nt++) {
                    mma8(acc[mt][nt], ah[mt], bh[nt]);
                    mma8(acc[mt][nt], ah[mt], bl[nt]);
                    mma8(acc[mt][nt], al[mt], bh[nt]);
                }
        }
        __syncthreads();
    }

    // Epilogue: bias, clamp k/v, scatter to [B,H,S,DK]
    #pragma unroll
    for (int mt = 0; mt < 4; mt++)
        #pragma unroll
        for (int i2 = 0; i2 < 2; i2++) {
            int m = m0 + wm * 64 + mt * 16 + g + i2 * 8;
            int b = m >> 11;
            int s = m & 2047;
            #pragma unroll
            for (int nt = 0; nt < 4; nt++)
                #pragma unroll
                for (int j2 = 0; j2 < 2; j2++) {
                    int n   = n0 + wn * 32 + nt * 8 + 2 * c + j2;
                    float v = acc[mt][nt][i2 * 2 + j2] + bias[n];
                    int t   = n >> 10;
                    int rem = n & 1023;
                    int h   = rem >> 6;
                    int ch  = rem & 63;
                    size_t didx = ((size_t)(b * HH + h) * SS + s) * DK + ch;
                    if (t == 0) {
                        g_q[didx] = v;
                    } else {
                        int aidx = (b * HH + h) * DK + ch;
                        const float* amin = (t == 1) ? akmin : avmin;
                        const float* amax = (t == 1) ? akmax : avmax;
                        float lo = fmaxf(v - EPSG, amin[aidx]);
                        float hi = fminf(v + EPSG, amax[aidx]);
                        lo = fminf(lo, hi);
                        float cl = fmaxf(lo, fminf(v, hi));
                        if (t == 1) g_k[didx] = cl; else g_v[didx] = cl;
                    }
                }
        }
}

// ---------------------------------------------------------------------------
// Kernel 2: flash attention, tensor-core QK^T and PV with 3xTF32.
// 128 queries/block, 64-key tiles, 8 warps (16 q rows each).
// ---------------------------------------------------------------------------
__global__ __launch_bounds__(256, 2) void attn_kernel()
{
    __shared__ float Ks[64 * 68];   // [key][dk], pad 68
    __shared__ float Vs[64 * 72];   // [key][dk], pad 72

    const int tid  = threadIdx.x;
    const int lane = tid & 31, warp = tid >> 5;
    const int g = lane >> 2, c = lane & 3;

    const int bh = blockIdx.y;
    const int q0 = blockIdx.x * 128;
    const int qrow0 = q0 + warp * 16;

    const float* qbase = g_q + (size_t)bh * SS * DK;
    const float* kbase = g_k + (size_t)bh * SS * DK;
    const float* vbase = g_v + (size_t)bh * SS * DK;

    // Q fragments (raw, pre-scaled by 1/sqrt(dk)); split to tf32 on the fly.
    float qr[8][4];
    #pragma unroll
    for (int kt = 0; kt < 8; kt++) {
        qr[kt][0] = 0.125f * qbase[(size_t)(qrow0 + g    ) * DK + kt * 8 + c    ];
        qr[kt][1] = 0.125f * qbase[(size_t)(qrow0 + g + 8) * DK + kt * 8 + c    ];
        qr[kt][2] = 0.125f * qbase[(size_t)(qrow0 + g    ) * DK + kt * 8 + c + 4];
        qr[kt][3] = 0.125f * qbase[(size_t)(qrow0 + g + 8) * DK + kt * 8 + c + 4];
    }

    float m_run[2] = {-1e30f, -1e30f};
    float l_run[2] = {0.f, 0.f};
    float o[8][4];
    #pragma unroll
    for (int dt = 0; dt < 8; dt++)
        #pragma unroll
        for (int i = 0; i < 4; i++) o[dt][i] = 0.f;

    for (int j0 = 0; j0 < SS; j0 += 64) {
        // Load K,V tiles (64x64 each)
        #pragma unroll
        for (int l = 0; l < 4; l++) {
            int f   = l * 256 + tid;
            int row = f >> 4;
            int c4  = f & 15;
            float4 kv = *(const float4*)(kbase + (size_t)(j0 + row) * DK + c4 * 4);
            *(float4*)&Ks[row * 68 + c4 * 4] = kv;
            float4 vv = *(const float4*)(vbase + (size_t)(j0 + row) * DK + c4 * 4);
            *(float4*)&Vs[row * 72 + c4 * 4] = vv;
        }
        __syncthreads();

        // S = Q K^T (scores), accumulated in mma C fragments
        float s[8][4];
        #pragma unroll
        for (int nt = 0; nt < 8; nt++)
            #pragma unroll
            for (int i = 0; i < 4; i++) s[nt][i] = 0.f;

        #pragma unroll
        for (int kt = 0; kt < 8; kt++) {
            unsigned qh[4], ql[4];
            #pragma unroll
            for (int i = 0; i < 4; i++) split_tf32(qr[kt][i], qh[i], ql[i]);
            #pragma unroll
            for (int nt = 0; nt < 8; nt++) {
                unsigned bhh[2], bll[2];
                split_tf32(Ks[(nt * 8 + g) * 68 + kt * 8 + c    ], bhh[0], bll[0]);
                split_tf32(Ks[(nt * 8 + g) * 68 + kt * 8 + c + 4], bhh[1], bll[1]);
                mma8(s[nt], qh, bhh);
                mma8(s[nt], qh, bll);
                mma8(s[nt], ql, bhh);
            }
        }

        // Online softmax (rows g and g+8; row spread over 4-lane group)
        float mx0 = -1e30f, mx1 = -1e30f;
        #pragma unroll
        for (int nt = 0; nt < 8; nt++) {
            mx0 = fmaxf(mx0, fmaxf(s[nt][0], s[nt][1]));
            mx1 = fmaxf(mx1, fmaxf(s[nt][2], s[nt][3]));
        }
        mx0 = fmaxf(mx0, __shfl_xor_sync(0xffffffffu, mx0, 1));
        mx0 = fmaxf(mx0, __shfl_xor_sync(0xffffffffu, mx0, 2));
        mx1 = fmaxf(mx1, __shfl_xor_sync(0xffffffffu, mx1, 1));
        mx1 = fmaxf(mx1, __shfl_xor_sync(0xffffffffu, mx1, 2));

        float mn0 = fmaxf(m_run[0], mx0);
        float mn1 = fmaxf(m_run[1], mx1);
        float corr0 = __expf(m_run[0] - mn0);
        float corr1 = __expf(m_run[1] - mn1);
        m_run[0] = mn0;
        m_run[1] = mn1;

        float ls0 = 0.f, ls1 = 0.f;
        #pragma unroll
        for (int nt = 0; nt < 8; nt++) {
            s[nt][0] = __expf(s[nt][0] - mn0);
            s[nt][1] = __expf(s[nt][1] - mn0);
            s[nt][2] = __expf(s[nt][2] - mn1);
            s[nt][3] = __expf(s[nt][3] - mn1);
            ls0 += s[nt][0] + s[nt][1];
            ls1 += s[nt][2] + s[nt][3];
        }
        ls0 += __shfl_xor_sync(0xffffffffu, ls0, 1);
        ls0 += __shfl_xor_sync(0xffffffffu, ls0, 2);
        ls1 += __shfl_xor_sync(0xffffffffu, ls1, 1);
        ls1 += __shfl_xor_sync(0xffffffffu, ls1, 2);
        l_run[0] = l_run[0] * corr0 + ls0;
        l_run[1] = l_run[1] * corr1 + ls1;

        #pragma unroll
        for (int dt = 0; dt < 8; dt++) {
            o[dt][0] *= corr0;
            o[dt][1] *= corr0;
            o[dt][2] *= corr1;
            o[dt][3] *= corr1;
        }

        // O += P V  (P in C-layout -> A-layout via shuffles)
        #pragma unroll
        for (int kt2 = 0; kt2 < 8; kt2++) {
            float pa0, pa1, pa2, pa3;
            c2a(s[kt2][0], s[kt2][1], s[kt2][2], s[kt2][3],
                pa0, pa1, pa2, pa3, lane);
            unsigned ph[4], pl[4];
            split_tf32(pa0, ph[0], pl[0]);
            split_tf32(pa1, ph[1], pl[1]);
            split_tf32(pa2, ph[2], pl[2]);
            split_tf32(pa3, ph[3], pl[3]);
            #pragma unroll
            for (int dt = 0; dt < 8; dt++) {
                unsigned vh[2], vl[2];
                split_tf32(Vs[(kt2 * 8 + c    ) * 72 + dt * 8 + g], vh[0], vl[0]);
                split_tf32(Vs[(kt2 * 8 + c + 4) * 72 + dt * 8 + g], vh[1], vl[1]);
                mma8(o[dt], ph, vh);
                mma8(o[dt], ph, vl);
                mma8(o[dt], pl, vh);
            }
        }
        __syncthreads();
    }

    // Normalize and store
    float* ob = g_ao + (size_t)bh * SS * DK;
    float inv0 = 1.f / l_run[0];
    float inv1 = 1.f / l_run[1];
    #pragma unroll
    for (int dt = 0; dt < 8; dt++) {
        float2 r0 = make_float2(o[dt][0] * inv0, o[dt][1] * inv0);
        *(float2*)(ob + (size_t)(qrow0 + g    ) * DK + dt * 8 + 2 * c) = r0;
        float2 r1 = make_float2(o[dt][2] * inv1, o[dt][3] * inv1);
        *(float2*)(ob + (size_t)(qrow0 + g + 8) * DK + dt * 8 + 2 * c) = r1;
    }
}

// ---------------------------------------------------------------------------
// Kernel 3: out = attn @ out_w^T + out_b. M=4096, N=1024, K=1024.
// Same 3xTF32 core; A gathered from g_ao [B,H,S,DK].
// ---------------------------------------------------------------------------
__global__ __launch_bounds__(256, 1) void out_gemm_kernel(
    const float* __restrict__ w,
    const float* __restrict__ bias,
    float* __restrict__ out)
{
    __shared__ float As[32 * 132];
    __shared__ float Bs[32 * 132];

    const int tid  = threadIdx.x;
    const int lane = tid & 31, warp = tid >> 5;
    const int g = lane >> 2, c = lane & 3;
    const int wm = warp >> 2, wn = warp & 3;
    const int m0 = blockIdx.y * 128, n0 = blockIdx.x * 128;

    float acc[4][4][4];
    #pragma unroll
    for (int mt = 0; mt < 4; mt++)
        #pragma unroll
        for (int nt = 0; nt < 4; nt++)
            #pragma unroll
            for (int i = 0; i < 4; i++) acc[mt][nt][i] = 0.f;

    for (int k0 = 0; k0 < DM; k0 += 32) {
        #pragma unroll
        for (int l = 0; l < 4; l++) {
            int f   = l * 256 + tid;
            int row = f >> 3;
            int c4  = f & 7;
            int m   = m0 + row;
            int b   = m >> 11;
            int s   = m & 2047;
            int kk  = k0 + c4 * 4;
            int h   = kk >> 6;
            int ch  = kk & 63;
            float4 v = *(const float4*)(g_ao + ((size_t)(b * HH + h) * SS + s) * DK + ch);
            As[(c4 * 4 + 0) * 132 + row] = v.x;
            As[(c4 * 4 + 1) * 132 + row] = v.y;
            As[(c4 * 4 + 2) * 132 + row] = v.z;
            As[(c4 * 4 + 3) * 132 + row] = v.w;
            float4 u = *(const float4*)(w + (size_t)(n0 + row) * DM + k0 + c4 * 4);
            Bs[(c4 * 4 + 0) * 132 + row] = u.x;
            Bs[(c4 * 4 + 1) * 132 + row] = u.y;
            Bs[(c4 * 4 + 2) * 132 + row] = u.z;
            Bs[(c4 * 4 + 3) * 132 + row] = u.w;
        }
        __syncthreads();

        #pragma unroll
        for (int ks = 0; ks < 32; ks += 8) {
            unsigned ah[4][4], al[4][4], bh[4][2], bl[4][2];
            #pragma unroll
            for (int mt = 0; mt < 4; mt++) {
                int mb = wm * 64 + mt * 16 + g;
                split_tf32(As[(ks + c    ) * 132 + mb    ], ah[mt][0], al[mt][0]);
                split_tf32(As[(ks + c    ) * 132 + mb + 8], ah[mt][1], al[mt][1]);
                split_tf32(As[(ks + c + 4) * 132 + mb    ], ah[mt][2], al[mt][2]);
                split_tf32(As[(ks + c + 4) * 132 + mb + 8], ah[mt][3], al[mt][3]);
            }
            #pragma unroll
            for (int nt = 0; nt < 4; nt++) {
                int nb = wn * 32 + nt * 8 + g;
                split_tf32(Bs[(ks + c    ) * 132 + nb], bh[nt][0], bl[nt][0]);
                split_tf32(Bs[(ks + c + 4) * 132 + nb], bh[nt][1], bl[nt][1]);
            }
            #pragma unroll
            for (int mt = 0; mt < 4; mt++)
                #pragma unroll
                for (int nt = 0; nt < 4; nt++) {
                    mma8(acc[mt][nt], ah[mt], bh[nt]);
                    mma8(acc[mt][nt], ah[mt], bl[nt]);
                    mma8(acc[mt][nt], al[mt], bh[nt]);
                }
        }
        __syncthreads();
    }

    #pragma unroll
    for (int mt = 0; mt < 4; mt++)
        #pragma unroll
        for (int i2 = 0; i2 < 2; i2++) {
            int m = m0 + wm * 64 + mt * 16 + g + i2 * 8;
            #pragma unroll
            for (int nt = 0; nt < 4; nt++) {
                int n = n0 + wn * 32 + nt * 8 + 2 * c;
                float2 r = make_float2(acc[mt][nt][i2 * 2 + 0] + bias[n],
                                       acc[mt][nt][i2 * 2 + 1] + bias[n + 1]);
                *(float2*)(out + (size_t)m * DM + n) = r;
            }
        }
}

// ---------------------------------------------------------------------------
extern "C" void kernel_launch(void* const* d_in, const int* in_sizes, int n_in,
                              void* d_out, int out_size)
{
    const float* x      = (const float*)d_in[0];
    const float* qkv_w  = (const float*)d_in[1];
    const float* qkv_b  = (const float*)d_in[2];
    const float* out_w  = (const float*)d_in[3];
    const float* out_b  = (const float*)d_in[4];
    const float* akmin  = (const float*)d_in[5];
    const float* akmax  = (const float*)d_in[6];
    const float* avmin  = (const float*)d_in[7];
    const float* avmax  = (const float*)d_in[8];
    float* out = (float*)d_out;

    qkv_gemm_kernel<<<dim3(NQKV / 128, MTOT / 128), 256>>>(
        x, qkv_w, qkv_b, akmin, akmax, avmin, avmax);

    attn_kernel<<<dim3(SS / 128, BB * HH), 256>>>();

    out_gemm_kernel<<<dim3(DM / 128, MTOT / 128), 256>>>(out_w, out_b, out);
}

// round 4
// speedup vs baseline: 2.0085x; 1.6270x over previous
#include <cuda_runtime.h>
#include <cuda_bf16.h>
#include <math.h>

// Problem constants
#define BB   2
#define SS   2048
#define DM   1024
#define HH   16
#define DK   64
#define NQKV 3072
#define MTOT 4096
#define EPSG 0.1f

// Packed bf16 hi/lo pair scratch (uint2 = {hi_pair, lo_pair}, 2 k-values each)
__device__ __align__(16) uint2 g_xp   [512 * 4096];      // x      [k2][m]
__device__ __align__(16) uint2 g_wqkvp[512 * 3072];      // qkv_w  [k2][n]
__device__ __align__(16) uint2 g_wop  [512 * 1024];      // out_w  [k2][n]
__device__ __align__(16) uint2 g_qp   [32 * 2048 * 32];  // q      [bh][s][dk2] (pre-scaled 1/8)
__device__ __align__(16) uint2 g_kp   [32 * 32 * 2048];  // k      [bh][dk2][s]
__device__ float           g_v  [32 * 2048 * 64];        // v clamped, float
__device__ __align__(16) uint2 g_vp   [32 * 1024 * 64];  // v      [bh][s2][dk] (key-pairs)
__device__ __align__(16) uint2 g_aop  [512 * 4096];      // attn out [k2][m]

// ---------------------------------------------------------------------------
// helpers
// ---------------------------------------------------------------------------
__device__ __forceinline__ uint2 pack2(float a, float b) {
    __nv_bfloat162 h = __floats2bfloat162_rn(a, b);
    float ra = a - __bfloat162float(h.x);
    float rb = b - __bfloat162float(h.y);
    __nv_bfloat162 l = __floats2bfloat162_rn(ra, rb);
    uint2 r;
    r.x = *reinterpret_cast<unsigned*>(&h);
    r.y = *reinterpret_cast<unsigned*>(&l);
    return r;
}

__device__ __forceinline__ void mma16(float* d, unsigned a0, unsigned a1,
                                      unsigned a2, unsigned a3,
                                      unsigned b0, unsigned b1) {
    asm volatile(
        "mma.sync.aligned.m16n8k16.row.col.f32.bf16.bf16.f32 "
        "{%0,%1,%2,%3}, {%4,%5,%6,%7}, {%8,%9}, {%0,%1,%2,%3};"
        : "+f"(d[0]), "+f"(d[1]), "+f"(d[2]), "+f"(d[3])
        : "r"(a0), "r"(a1), "r"(a2), "r"(a3), "r"(b0), "r"(b1));
}

__device__ __forceinline__ float clampg(float v, float amn, float amx) {
    float lo = fmaxf(v - EPSG, amn);
    float hi = fminf(v + EPSG, amx);
    lo = fminf(lo, hi);
    return fmaxf(lo, fminf(v, hi));
}

// ---------------------------------------------------------------------------
// Pre-pass: transpose-convert float [R][1024] row-major -> uint2 [512][R]
// which: 0 -> g_xp, 1 -> g_wqkvp, 2 -> g_wop
// ---------------------------------------------------------------------------
__global__ __launch_bounds__(256) void conv_t_kernel(
    const float* __restrict__ in, int which, int R)
{
    __shared__ float t[32][68];
    uint2* out = (which == 0) ? g_xp : (which == 1) ? g_wqkvp : g_wop;
    int r0 = blockIdx.x * 32;
    int k0 = blockIdx.y * 64;
    int tid = threadIdx.x;
    #pragma unroll
    for (int l = 0; l < 2; l++) {
        int idx = l * 256 + tid;
        int rr = idx >> 4, c4 = idx & 15;
        float4 v = *(const float4*)(in + (size_t)(r0 + rr) * 1024 + k0 + c4 * 4);
        t[rr][c4 * 4 + 0] = v.x;
        t[rr][c4 * 4 + 1] = v.y;
        t[rr][c4 * 4 + 2] = v.z;
        t[rr][c4 * 4 + 3] = v.w;
    }
    __syncthreads();
    int K20 = k0 >> 1;
    #pragma unroll
    for (int l = 0; l < 4; l++) {
        int idx = l * 256 + tid;
        int k2l = idx >> 5, r = idx & 31;
        out[(size_t)(K20 + k2l) * R + r0 + r] = pack2(t[r][2 * k2l], t[r][2 * k2l + 1]);
    }
}

// ---------------------------------------------------------------------------
// Pre-pass: g_v float [bh][s][dk] -> g_vp packed key-pairs [bh][s2][dk]
// ---------------------------------------------------------------------------
__global__ __launch_bounds__(256) void conv_v_kernel()
{
    int idx = blockIdx.x * 256 + threadIdx.x;      // 32*1024*64 = 2M
    int d   = idx & 63;
    int s2  = (idx >> 6) & 1023;
    int bh  = idx >> 16;
    const float* src = g_v + ((size_t)bh * SS + s2 * 2) * DK + d;
    g_vp[((size_t)bh * 1024 + s2) * 64 + d] = pack2(src[0], src[DK]);
}

// ---------------------------------------------------------------------------
// Kernel 1: qkv GEMM (M=4096, N=3072, K=1024), bf16x3, fused clamp/scatter.
// Block 128x128, ktile 32 floats (16 pairs), 8 warps 2x4, warp tile 64x32.
// ---------------------------------------------------------------------------
__global__ __launch_bounds__(256) void qkv_gemm_kernel(
    const float* __restrict__ bias,
    const float* __restrict__ akmin, const float* __restrict__ akmax,
    const float* __restrict__ avmin, const float* __restrict__ avmax)
{
    __shared__ __align__(16) uint2 As[16 * 136];
    __shared__ __align__(16) uint2 Bs[16 * 136];

    const int tid  = threadIdx.x;
    const int lane = tid & 31, warp = tid >> 5;
    const int g = lane >> 2, c = lane & 3;
    const int wm = warp >> 2, wn = warp & 3;
    const int m0 = blockIdx.y * 128, n0 = blockIdx.x * 128;

    float acc[4][4][4];
    #pragma unroll
    for (int mt = 0; mt < 4; mt++)
        #pragma unroll
        for (int nt = 0; nt < 4; nt++)
            #pragma unroll
            for (int i = 0; i < 4; i++) acc[mt][nt][i] = 0.f;

    for (int k0 = 0; k0 < 512; k0 += 16) {
        #pragma unroll
        for (int l = 0; l < 4; l++) {
            int idx = l * 256 + tid;
            int k2l = idx >> 6, m4 = idx & 63;
            uint4 va = *(const uint4*)(g_xp + (size_t)(k0 + k2l) * MTOT + m0 + m4 * 2);
            *(uint4*)&As[k2l * 136 + m4 * 2] = va;
            uint4 vb = *(const uint4*)(g_wqkvp + (size_t)(k0 + k2l) * NQKV + n0 + m4 * 2);
            *(uint4*)&Bs[k2l * 136 + m4 * 2] = vb;
        }
        __syncthreads();

        #pragma unroll
        for (int ks = 0; ks < 16; ks += 8) {
            uint2 a[4][4];
            #pragma unroll
            for (int mt = 0; mt < 4; mt++) {
                int mb = wm * 64 + mt * 16 + g;
                a[mt][0] = As[(ks + c    ) * 136 + mb];
                a[mt][1] = As[(ks + c    ) * 136 + mb + 8];
                a[mt][2] = As[(ks + c + 4) * 136 + mb];
                a[mt][3] = As[(ks + c + 4) * 136 + mb + 8];
            }
            #pragma unroll
            for (int nt = 0; nt < 4; nt++) {
                int nb = wn * 32 + nt * 8 + g;
                uint2 b0 = Bs[(ks + c    ) * 136 + nb];
                uint2 b1 = Bs[(ks + c + 4) * 136 + nb];
                #pragma unroll
                for (int mt = 0; mt < 4; mt++) {
                    mma16(acc[mt][nt], a[mt][0].x, a[mt][1].x, a[mt][2].x, a[mt][3].x, b0.x, b1.x);
                    mma16(acc[mt][nt], a[mt][0].x, a[mt][1].x, a[mt][2].x, a[mt][3].x, b0.y, b1.y);
                    mma16(acc[mt][nt], a[mt][0].y, a[mt][1].y, a[mt][2].y, a[mt][3].y, b0.x, b1.x);
                }
            }
        }
        __syncthreads();
    }

    // Epilogue: bias, clamp, pack pairs, scatter.
    #pragma unroll
    for (int mt = 0; mt < 4; mt++)
        #pragma unroll
        for (int i2 = 0; i2 < 2; i2++) {
            int m = m0 + wm * 64 + mt * 16 + g + i2 * 8;
            int b = m >> 11, s = m & 2047;
            #pragma unroll
            for (int nt = 0; nt < 4; nt++) {
                int n = n0 + wn * 32 + nt * 8 + 2 * c;
                float v0 = acc[mt][nt][i2 * 2 + 0] + bias[n];
                float v1 = acc[mt][nt][i2 * 2 + 1] + bias[n + 1];
                int t = n >> 10, rem = n & 1023, h = rem >> 6, ch = rem & 63;
                int bh = b * HH + h;
                if (t == 0) {
                    g_qp[((size_t)bh * SS + s) * 32 + (ch >> 1)] =
                        pack2(v0 * 0.125f, v1 * 0.125f);
                } else if (t == 1) {
                    int ai = bh * DK + ch;
                    float c0 = clampg(v0, akmin[ai], akmax[ai]);
                    float c1 = clampg(v1, akmin[ai + 1], akmax[ai + 1]);
                    g_kp[((size_t)bh * 32 + (ch >> 1)) * SS + s] = pack2(c0, c1);
                } else {
                    int ai = bh * DK + ch;
                    float c0 = clampg(v0, avmin[ai], avmax[ai]);
                    float c1 = clampg(v1, avmin[ai + 1], avmax[ai + 1]);
                    *(float2*)(g_v + ((size_t)bh * SS + s) * DK + ch) =
                        make_float2(c0, c1);
                }
            }
        }
}

// ---------------------------------------------------------------------------
// Kernel 2: flash attention, bf16x3 tensor core. 128 q/block, 64-key tiles,
// 8 warps x 16 q rows. Q pre-packed in regs; K,V pre-packed tiles in smem.
// P C-frag == A-frag layout (f16 family): no shuffles.
// ---------------------------------------------------------------------------
__global__ __launch_bounds__(256, 2) void attn_kernel()
{
    __shared__ __align__(16) uint2 Ks[32 * 72];
    __shared__ __align__(16) uint2 Vs[32 * 72];

    const int tid  = threadIdx.x;
    const int lane = tid & 31, warp = tid >> 5;
    const int g = lane >> 2, c = lane & 3;
    const int bh = blockIdx.y;
    const int qrow0 = blockIdx.x * 128 + warp * 16;

    uint2 q[4][4];
    const uint2* qp = g_qp + (size_t)bh * SS * 32;
    #pragma unroll
    for (int kt = 0; kt < 4; kt++) {
        q[kt][0] = qp[(size_t)(qrow0 + g    ) * 32 + kt * 8 + c];
        q[kt][1] = qp[(size_t)(qrow0 + g + 8) * 32 + kt * 8 + c];
        q[kt][2] = qp[(size_t)(qrow0 + g    ) * 32 + kt * 8 + c + 4];
        q[kt][3] = qp[(size_t)(qrow0 + g + 8) * 32 + kt * 8 + c + 4];
    }

    float m0r = -1e30f, m1r = -1e30f, l0r = 0.f, l1r = 0.f;
    float o[8][4];
    #pragma unroll
    for (int dt = 0; dt < 8; dt++)
        #pragma unroll
        for (int i = 0; i < 4; i++) o[dt][i] = 0.f;

    const uint2* kpb = g_kp + (size_t)bh * 32 * SS;
    const uint2* vpb = g_vp + (size_t)bh * 1024 * 64;

    for (int j0 = 0; j0 < SS; j0 += 64) {
        #pragma unroll
        for (int l = 0; l < 4; l++) {
            int idx = l * 256 + tid;
            int row = idx >> 5, c2 = idx & 31;
            uint4 kv = *(const uint4*)(kpb + (size_t)row * SS + j0 + c2 * 2);
            *(uint4*)&Ks[row * 72 + c2 * 2] = kv;
            uint4 vv = *(const uint4*)(vpb + (size_t)((j0 >> 1) + row) * 64 + c2 * 2);
            *(uint4*)&Vs[row * 72 + c2 * 2] = vv;
        }
        __syncthreads();

        // S = Q K^T
        float s[8][4];
        #pragma unroll
        for (int nt = 0; nt < 8; nt++)
            #pragma unroll
            for (int i = 0; i < 4; i++) s[nt][i] = 0.f;

        #pragma unroll
        for (int kt = 0; kt < 4; kt++)
            #pragma unroll
            for (int nt = 0; nt < 8; nt++) {
                uint2 b0 = Ks[(kt * 8 + c    ) * 72 + nt * 8 + g];
                uint2 b1 = Ks[(kt * 8 + c + 4) * 72 + nt * 8 + g];
                mma16(s[nt], q[kt][0].x, q[kt][1].x, q[kt][2].x, q[kt][3].x, b0.x, b1.x);
                mma16(s[nt], q[kt][0].x, q[kt][1].x, q[kt][2].x, q[kt][3].x, b0.y, b1.y);
                mma16(s[nt], q[kt][0].y, q[kt][1].y, q[kt][2].y, q[kt][3].y, b0.x, b1.x);
            }

        // Online softmax (rows g / g+8, spread over the 4-lane group)
        float mx0 = -1e30f, mx1 = -1e30f;
        #pragma unroll
        for (int nt = 0; nt < 8; nt++) {
            mx0 = fmaxf(mx0, fmaxf(s[nt][0], s[nt][1]));
            mx1 = fmaxf(mx1, fmaxf(s[nt][2], s[nt][3]));
        }
        mx0 = fmaxf(mx0, __shfl_xor_sync(0xffffffffu, mx0, 1));
        mx0 = fmaxf(mx0, __shfl_xor_sync(0xffffffffu, mx0, 2));
        mx1 = fmaxf(mx1, __shfl_xor_sync(0xffffffffu, mx1, 1));
        mx1 = fmaxf(mx1, __shfl_xor_sync(0xffffffffu, mx1, 2));

        float mn0 = fmaxf(m0r, mx0), mn1 = fmaxf(m1r, mx1);
        float corr0 = __expf(m0r - mn0), corr1 = __expf(m1r - mn1);
        m0r = mn0; m1r = mn1;

        float ls0 = 0.f, ls1 = 0.f;
        #pragma unroll
        for (int nt = 0; nt < 8; nt++) {
            s[nt][0] = __expf(s[nt][0] - mn0);
            s[nt][1] = __expf(s[nt][1] - mn0);
            s[nt][2] = __expf(s[nt][2] - mn1);
            s[nt][3] = __expf(s[nt][3] - mn1);
            ls0 += s[nt][0] + s[nt][1];
            ls1 += s[nt][2] + s[nt][3];
        }
        ls0 += __shfl_xor_sync(0xffffffffu, ls0, 1);
        ls0 += __shfl_xor_sync(0xffffffffu, ls0, 2);
        ls1 += __shfl_xor_sync(0xffffffffu, ls1, 1);
        ls1 += __shfl_xor_sync(0xffffffffu, ls1, 2);
        l0r = l0r * corr0 + ls0;
        l1r = l1r * corr1 + ls1;

        #pragma unroll
        for (int dt = 0; dt < 8; dt++) {
            o[dt][0] *= corr0; o[dt][1] *= corr0;
            o[dt][2] *= corr1; o[dt][3] *= corr1;
        }

        // O += P V  (C-frag of S is exactly the A-frag of P)
        #pragma unroll
        for (int t = 0; t < 4; t++) {
            uint2 p0 = pack2(s[2 * t    ][0], s[2 * t    ][1]);
            uint2 p1 = pack2(s[2 * t    ][2], s[2 * t    ][3]);
            uint2 p2 = pack2(s[2 * t + 1][0], s[2 * t + 1][1]);
            uint2 p3 = pack2(s[2 * t + 1][2], s[2 * t + 1][3]);
            #pragma unroll
            for (int dt = 0; dt < 8; dt++) {
                uint2 b0 = Vs[(t * 8 + c    ) * 72 + dt * 8 + g];
                uint2 b1 = Vs[(t * 8 + c + 4) * 72 + dt * 8 + g];
                mma16(o[dt], p0.x, p1.x, p2.x, p3.x, b0.x, b1.x);
                mma16(o[dt], p0.x, p1.x, p2.x, p3.x, b0.y, b1.y);
                mma16(o[dt], p0.y, p1.y, p2.y, p3.y, b0.x, b1.x);
            }
        }
        __syncthreads();
    }

    // Normalize + pack pairs + scatter to [k2][m]
    int b = bh >> 4, h = bh & 15;
    float inv0 = 1.f / l0r, inv1 = 1.f / l1r;
    size_t mbase = (size_t)b * SS + qrow0;
    #pragma unroll
    for (int dt = 0; dt < 8; dt++) {
        size_t k2g = h * 32 + dt * 4 + c;
        g_aop[k2g * MTOT + mbase + g    ] = pack2(o[dt][0] * inv0, o[dt][1] * inv0);
        g_aop[k2g * MTOT + mbase + g + 8] = pack2(o[dt][2] * inv1, o[dt][3] * inv1);
    }
}

// ---------------------------------------------------------------------------
// Kernel 3: out = attn @ out_w^T + out_b (M=4096, N=1024, K=1024), bf16x3.
// ---------------------------------------------------------------------------
__global__ __launch_bounds__(256) void out_gemm_kernel(
    const float* __restrict__ bias, float* __restrict__ out)
{
    __shared__ __align__(16) uint2 As[16 * 136];
    __shared__ __align__(16) uint2 Bs[16 * 136];

    const int tid  = threadIdx.x;
    const int lane = tid & 31, warp = tid >> 5;
    const int g = lane >> 2, c = lane & 3;
    const int wm = warp >> 2, wn = warp & 3;
    const int m0 = blockIdx.y * 128, n0 = blockIdx.x * 128;

    float acc[4][4][4];
    #pragma unroll
    for (int mt = 0; mt < 4; mt++)
        #pragma unroll
        for (int nt = 0; nt < 4; nt++)
            #pragma unroll
            for (int i = 0; i < 4; i++) acc[mt][nt][i] = 0.f;

    for (int k0 = 0; k0 < 512; k0 += 16) {
        #pragma unroll
        for (int l = 0; l < 4; l++) {
            int idx = l * 256 + tid;
            int k2l = idx >> 6, m4 = idx & 63;
            uint4 va = *(const uint4*)(g_aop + (size_t)(k0 + k2l) * MTOT + m0 + m4 * 2);
            *(uint4*)&As[k2l * 136 + m4 * 2] = va;
            uint4 vb = *(const uint4*)(g_wop + (size_t)(k0 + k2l) * DM + n0 + m4 * 2);
            *(uint4*)&Bs[k2l * 136 + m4 * 2] = vb;
        }
        __syncthreads();

        #pragma unroll
        for (int ks = 0; ks < 16; ks += 8) {
            uint2 a[4][4];
            #pragma unroll
            for (int mt = 0; mt < 4; mt++) {
                int mb = wm * 64 + mt * 16 + g;
                a[mt][0] = As[(ks + c    ) * 136 + mb];
                a[mt][1] = As[(ks + c    ) * 136 + mb + 8];
                a[mt][2] = As[(ks + c + 4) * 136 + mb];
                a[mt][3] = As[(ks + c + 4) * 136 + mb + 8];
            }
            #pragma unroll
            for (int nt = 0; nt < 4; nt++) {
                int nb = wn * 32 + nt * 8 + g;
                uint2 b0 = Bs[(ks + c    ) * 136 + nb];
                uint2 b1 = Bs[(ks + c + 4) * 136 + nb];
                #pragma unroll
                for (int mt = 0; mt < 4; mt++) {
                    mma16(acc[mt][nt], a[mt][0].x, a[mt][1].x, a[mt][2].x, a[mt][3].x, b0.x, b1.x);
                    mma16(acc[mt][nt], a[mt][0].x, a[mt][1].x, a[mt][2].x, a[mt][3].x, b0.y, b1.y);
                    mma16(acc[mt][nt], a[mt][0].y, a[mt][1].y, a[mt][2].y, a[mt][3].y, b0.x, b1.x);
                }
            }
        }
        __syncthreads();
    }

    #pragma unroll
    for (int mt = 0; mt < 4; mt++)
        #pragma unroll
        for (int i2 = 0; i2 < 2; i2++) {
            int m = m0 + wm * 64 + mt * 16 + g + i2 * 8;
            #pragma unroll
            for (int nt = 0; nt < 4; nt++) {
                int n = n0 + wn * 32 + nt * 8 + 2 * c;
                float2 r = make_float2(acc[mt][nt][i2 * 2 + 0] + bias[n],
                                       acc[mt][nt][i2 * 2 + 1] + bias[n + 1]);
                *(float2*)(out + (size_t)m * DM + n) = r;
            }
        }
}

// ---------------------------------------------------------------------------
extern "C" void kernel_launch(void* const* d_in, const int* in_sizes, int n_in,
                              void* d_out, int out_size)
{
    const float* x      = (const float*)d_in[0];
    const float* qkv_w  = (const float*)d_in[1];
    const float* qkv_b  = (const float*)d_in[2];
    const float* out_w  = (const float*)d_in[3];
    const float* out_b  = (const float*)d_in[4];
    const float* akmin  = (const float*)d_in[5];
    const float* akmax  = (const float*)d_in[6];
    const float* avmin  = (const float*)d_in[7];
    const float* avmax  = (const float*)d_in[8];
    float* out = (float*)d_out;

    conv_t_kernel<<<dim3(MTOT / 32, 16), 256>>>(x,     0, MTOT);
    conv_t_kernel<<<dim3(NQKV / 32, 16), 256>>>(qkv_w, 1, NQKV);
    conv_t_kernel<<<dim3(DM   / 32, 16), 256>>>(out_w, 2, DM);

    qkv_gemm_kernel<<<dim3(NQKV / 128, MTOT / 128), 256>>>(
        qkv_b, akmin, akmax, avmin, avmax);

    conv_v_kernel<<<8192, 256>>>();

    attn_kernel<<<dim3(SS / 128, BB * HH), 256>>>();

    out_gemm_kernel<<<dim3(DM / 128, MTOT / 128), 256>>>(out_b, out);
}

// round 5
// speedup vs baseline: 2.2984x; 1.1443x over previous
#include <cuda_runtime.h>
#include <cuda_bf16.h>
#include <math.h>

// Problem constants
#define BB   2
#define SS   2048
#define DM   1024
#define HH   16
#define DK   64
#define NQKV 3072
#define MTOT 4096
#define EPSG 0.1f

// Packed bf16 hi/lo pair scratch (uint2 = {hi_pair, lo_pair}, 2 k-values each)
__device__ __align__(16) uint2 g_xp   [512 * 4096];      // x      [k2][m]
__device__ __align__(16) uint2 g_wqkvp[512 * 3072];      // qkv_w  [k2][n]
__device__ __align__(16) uint2 g_wop  [512 * 1024];      // out_w  [k2][n]
__device__ __align__(16) uint2 g_qp   [32 * 2048 * 32];  // q      [bh][s][dk2] (pre-scaled 1/8)
__device__ __align__(16) uint2 g_kp   [32 * 32 * 2048];  // k      [bh][dk2][s]
__device__ float           g_v  [32 * 2048 * 64];        // v clamped, float
__device__ __align__(16) uint2 g_vp   [32 * 1024 * 64];  // v      [bh][s2][dk] (key-pairs)
__device__ __align__(16) uint2 g_aop  [512 * 4096];      // attn out [k2][m]

// ---------------------------------------------------------------------------
// helpers
// ---------------------------------------------------------------------------
__device__ __forceinline__ uint2 pack2(float a, float b) {
    __nv_bfloat162 h = __floats2bfloat162_rn(a, b);
    float ra = a - __bfloat162float(h.x);
    float rb = b - __bfloat162float(h.y);
    __nv_bfloat162 l = __floats2bfloat162_rn(ra, rb);
    uint2 r;
    r.x = *reinterpret_cast<unsigned*>(&h);
    r.y = *reinterpret_cast<unsigned*>(&l);
    return r;
}

__device__ __forceinline__ void mma16(float* d, unsigned a0, unsigned a1,
                                      unsigned a2, unsigned a3,
                                      unsigned b0, unsigned b1) {
    asm volatile(
        "mma.sync.aligned.m16n8k16.row.col.f32.bf16.bf16.f32 "
        "{%0,%1,%2,%3}, {%4,%5,%6,%7}, {%8,%9}, {%0,%1,%2,%3};"
        : "+f"(d[0]), "+f"(d[1]), "+f"(d[2]), "+f"(d[3])
        : "r"(a0), "r"(a1), "r"(a2), "r"(a3), "r"(b0), "r"(b1));
}

__device__ __forceinline__ float clampg(float v, float amn, float amx) {
    float lo = fmaxf(v - EPSG, amn);
    float hi = fminf(v + EPSG, amx);
    lo = fminf(lo, hi);
    return fmaxf(lo, fminf(v, hi));
}

__device__ __forceinline__ void cp16(void* sdst, const void* gsrc) {
    unsigned s = (unsigned)__cvta_generic_to_shared(sdst);
    size_t   g = __cvta_generic_to_global(gsrc);
    asm volatile("cp.async.cg.shared.global [%0], [%1], 16;"
                 :: "r"(s), "l"(g) : "memory");
}
#define CP_COMMIT() asm volatile("cp.async.commit_group;" ::: "memory")
#define CP_WAIT1()  asm volatile("cp.async.wait_group 1;" ::: "memory")

// ---------------------------------------------------------------------------
// Pre-pass: transpose-convert float [R][1024] row-major -> uint2 [512][R]
// which: 0 -> g_xp, 1 -> g_wqkvp, 2 -> g_wop
// ---------------------------------------------------------------------------
__global__ __launch_bounds__(256) void conv_t_kernel(
    const float* __restrict__ in, int which, int R)
{
    __shared__ float t[32][68];
    uint2* out = (which == 0) ? g_xp : (which == 1) ? g_wqkvp : g_wop;
    int r0 = blockIdx.x * 32;
    int k0 = blockIdx.y * 64;
    int tid = threadIdx.x;
    #pragma unroll
    for (int l = 0; l < 2; l++) {
        int idx = l * 256 + tid;
        int rr = idx >> 4, c4 = idx & 15;
        float4 v = *(const float4*)(in + (size_t)(r0 + rr) * 1024 + k0 + c4 * 4);
        t[rr][c4 * 4 + 0] = v.x;
        t[rr][c4 * 4 + 1] = v.y;
        t[rr][c4 * 4 + 2] = v.z;
        t[rr][c4 * 4 + 3] = v.w;
    }
    __syncthreads();
    int K20 = k0 >> 1;
    #pragma unroll
    for (int l = 0; l < 4; l++) {
        int idx = l * 256 + tid;
        int k2l = idx >> 5, r = idx & 31;
        out[(size_t)(K20 + k2l) * R + r0 + r] = pack2(t[r][2 * k2l], t[r][2 * k2l + 1]);
    }
}

// ---------------------------------------------------------------------------
// Pre-pass: g_v float [bh][s][dk] -> g_vp packed key-pairs [bh][s2][dk]
// ---------------------------------------------------------------------------
__global__ __launch_bounds__(256) void conv_v_kernel()
{
    int idx = blockIdx.x * 256 + threadIdx.x;
    int d   = idx & 63;
    int s2  = (idx >> 6) & 1023;
    int bh  = idx >> 16;
    const float* src = g_v + ((size_t)bh * SS + s2 * 2) * DK + d;
    g_vp[((size_t)bh * 1024 + s2) * 64 + d] = pack2(src[0], src[DK]);
}

// ---------------------------------------------------------------------------
// Kernel 1: qkv GEMM (M=4096, N=3072, K=1024), bf16x3, fused clamp/scatter.
// Block 128x128, ktile 32 floats (16 pairs), cp.async 2-stage double buffer.
// Dynamic smem: 2 stages x (As 16*136 + Bs 16*136) uint2 = 69632 B.
// ---------------------------------------------------------------------------
#define GEMM_STG 2176   // 16*136 uint2 per array per stage

__global__ __launch_bounds__(256) void qkv_gemm_kernel(
    const float* __restrict__ bias,
    const float* __restrict__ akmin, const float* __restrict__ akmax,
    const float* __restrict__ avmin, const float* __restrict__ avmax)
{
    extern __shared__ __align__(16) uint2 dsm[];
    uint2* As = dsm;                 // [2][16*136]
    uint2* Bs = dsm + 2 * GEMM_STG;  // [2][16*136]

    const int tid  = threadIdx.x;
    const int lane = tid & 31, warp = tid >> 5;
    const int g = lane >> 2, c = lane & 3;
    const int wm = warp >> 2, wn = warp & 3;
    const int m0 = blockIdx.y * 128, n0 = blockIdx.x * 128;

    float acc[4][4][4];
    #pragma unroll
    for (int mt = 0; mt < 4; mt++)
        #pragma unroll
        for (int nt = 0; nt < 4; nt++)
            #pragma unroll
            for (int i = 0; i < 4; i++) acc[mt][nt][i] = 0.f;

    auto copy_tile = [&](int stage, int k0) {
        uint2* Ad = As + stage * GEMM_STG;
        uint2* Bd = Bs + stage * GEMM_STG;
        #pragma unroll
        for (int l = 0; l < 4; l++) {
            int idx = l * 256 + tid;
            int k2l = idx >> 6, m4 = idx & 63;
            cp16(&Ad[k2l * 136 + m4 * 2],
                 g_xp + (size_t)(k0 + k2l) * MTOT + m0 + m4 * 2);
            cp16(&Bd[k2l * 136 + m4 * 2],
                 g_wqkvp + (size_t)(k0 + k2l) * NQKV + n0 + m4 * 2);
        }
    };

    copy_tile(0, 0);
    CP_COMMIT();

    for (int it = 0; it < 32; it++) {
        if (it + 1 < 32) copy_tile((it + 1) & 1, (it + 1) * 16);
        CP_COMMIT();
        CP_WAIT1();
        __syncthreads();

        const uint2* Ac = As + (it & 1) * GEMM_STG;
        const uint2* Bc = Bs + (it & 1) * GEMM_STG;

        #pragma unroll
        for (int ks = 0; ks < 16; ks += 8) {
            uint2 a[4][4];
            #pragma unroll
            for (int mt = 0; mt < 4; mt++) {
                int mb = wm * 64 + mt * 16 + g;
                a[mt][0] = Ac[(ks + c    ) * 136 + mb];
                a[mt][1] = Ac[(ks + c    ) * 136 + mb + 8];
                a[mt][2] = Ac[(ks + c + 4) * 136 + mb];
                a[mt][3] = Ac[(ks + c + 4) * 136 + mb + 8];
            }
            #pragma unroll
            for (int nt = 0; nt < 4; nt++) {
                int nb = wn * 32 + nt * 8 + g;
                uint2 b0 = Bc[(ks + c    ) * 136 + nb];
                uint2 b1 = Bc[(ks + c + 4) * 136 + nb];
                #pragma unroll
                for (int mt = 0; mt < 4; mt++) {
                    mma16(acc[mt][nt], a[mt][0].x, a[mt][1].x, a[mt][2].x, a[mt][3].x, b0.x, b1.x);
                    mma16(acc[mt][nt], a[mt][0].x, a[mt][1].x, a[mt][2].x, a[mt][3].x, b0.y, b1.y);
                    mma16(acc[mt][nt], a[mt][0].y, a[mt][1].y, a[mt][2].y, a[mt][3].y, b0.x, b1.x);
                }
            }
        }
        __syncthreads();
    }

    // Epilogue: bias, clamp, pack pairs, scatter.
    #pragma unroll
    for (int mt = 0; mt < 4; mt++)
        #pragma unroll
        for (int i2 = 0; i2 < 2; i2++) {
            int m = m0 + wm * 64 + mt * 16 + g + i2 * 8;
            int b = m >> 11, s = m & 2047;
            #pragma unroll
            for (int nt = 0; nt < 4; nt++) {
                int n = n0 + wn * 32 + nt * 8 + 2 * c;
                float v0 = acc[mt][nt][i2 * 2 + 0] + bias[n];
                float v1 = acc[mt][nt][i2 * 2 + 1] + bias[n + 1];
                int t = n >> 10, rem = n & 1023, h = rem >> 6, ch = rem & 63;
                int bh = b * HH + h;
                if (t == 0) {
                    g_qp[((size_t)bh * SS + s) * 32 + (ch >> 1)] =
                        pack2(v0 * 0.125f, v1 * 0.125f);
                } else if (t == 1) {
                    int ai = bh * DK + ch;
                    float c0 = clampg(v0, akmin[ai], akmax[ai]);
                    float c1 = clampg(v1, akmin[ai + 1], akmax[ai + 1]);
                    g_kp[((size_t)bh * 32 + (ch >> 1)) * SS + s] = pack2(c0, c1);
                } else {
                    int ai = bh * DK + ch;
                    float c0 = clampg(v0, avmin[ai], avmax[ai]);
                    float c1 = clampg(v1, avmin[ai + 1], avmax[ai + 1]);
                    *(float2*)(g_v + ((size_t)bh * SS + s) * DK + ch) =
                        make_float2(c0, c1);
                }
            }
        }
}

// ---------------------------------------------------------------------------
// Kernel 2: flash attention, bf16x3 tensor core, cp.async double-buffered
// K/V tiles. 128 q/block, 64-key tiles, 8 warps x 16 q rows.
// Dynamic smem: 2 stages x (Ks 32*72 + Vs 32*72) uint2 = 73728 B.
// ---------------------------------------------------------------------------
#define ATT_STG 4608    // (32*72)*2 uint2 per stage (K then V)

__global__ __launch_bounds__(256, 2) void attn_kernel()
{
    extern __shared__ __align__(16) uint2 dsm[];

    const int tid  = threadIdx.x;
    const int lane = tid & 31, warp = tid >> 5;
    const int g = lane >> 2, c = lane & 3;
    const int bh = blockIdx.y;
    const int qrow0 = blockIdx.x * 128 + warp * 16;

    uint2 q[4][4];
    const uint2* qp = g_qp + (size_t)bh * SS * 32;
    #pragma unroll
    for (int kt = 0; kt < 4; kt++) {
        q[kt][0] = qp[(size_t)(qrow0 + g    ) * 32 + kt * 8 + c];
        q[kt][1] = qp[(size_t)(qrow0 + g + 8) * 32 + kt * 8 + c];
        q[kt][2] = qp[(size_t)(qrow0 + g    ) * 32 + kt * 8 + c + 4];
        q[kt][3] = qp[(size_t)(qrow0 + g + 8) * 32 + kt * 8 + c + 4];
    }

    float m0r = -1e30f, m1r = -1e30f, l0r = 0.f, l1r = 0.f;
    float o[8][4];
    #pragma unroll
    for (int dt = 0; dt < 8; dt++)
        #pragma unroll
        for (int i = 0; i < 4; i++) o[dt][i] = 0.f;

    const uint2* kpb = g_kp + (size_t)bh * 32 * SS;
    const uint2* vpb = g_vp + (size_t)bh * 1024 * 64;

    auto copy_tile = [&](int stage, int j0) {
        uint2* Kd = dsm + stage * ATT_STG;
        uint2* Vd = Kd + 32 * 72;
        #pragma unroll
        for (int l = 0; l < 4; l++) {
            int idx = l * 256 + tid;
            int row = idx >> 5, c2 = idx & 31;
            cp16(&Kd[row * 72 + c2 * 2], kpb + (size_t)row * SS + j0 + c2 * 2);
            cp16(&Vd[row * 72 + c2 * 2],
                 vpb + (size_t)((j0 >> 1) + row) * 64 + c2 * 2);
        }
    };

    copy_tile(0, 0);
    CP_COMMIT();

    for (int jt = 0; jt < 32; jt++) {
        if (jt + 1 < 32) copy_tile((jt + 1) & 1, (jt + 1) * 64);
        CP_COMMIT();
        CP_WAIT1();
        __syncthreads();

        const uint2* Ks = dsm + (jt & 1) * ATT_STG;
        const uint2* Vs = Ks + 32 * 72;

        // S = Q K^T
        float s[8][4];
        #pragma unroll
        for (int nt = 0; nt < 8; nt++)
            #pragma unroll
            for (int i = 0; i < 4; i++) s[nt][i] = 0.f;

        #pragma unroll
        for (int kt = 0; kt < 4; kt++)
            #pragma unroll
            for (int nt = 0; nt < 8; nt++) {
                uint2 b0 = Ks[(kt * 8 + c    ) * 72 + nt * 8 + g];
                uint2 b1 = Ks[(kt * 8 + c + 4) * 72 + nt * 8 + g];
                mma16(s[nt], q[kt][0].x, q[kt][1].x, q[kt][2].x, q[kt][3].x, b0.x, b1.x);
                mma16(s[nt], q[kt][0].x, q[kt][1].x, q[kt][2].x, q[kt][3].x, b0.y, b1.y);
                mma16(s[nt], q[kt][0].y, q[kt][1].y, q[kt][2].y, q[kt][3].y, b0.x, b1.x);
            }

        // Online softmax (rows g / g+8, spread over the 4-lane group)
        float mx0 = -1e30f, mx1 = -1e30f;
        #pragma unroll
        for (int nt = 0; nt < 8; nt++) {
            mx0 = fmaxf(mx0, fmaxf(s[nt][0], s[nt][1]));
            mx1 = fmaxf(mx1, fmaxf(s[nt][2], s[nt][3]));
        }
        mx0 = fmaxf(mx0, __shfl_xor_sync(0xffffffffu, mx0, 1));
        mx0 = fmaxf(mx0, __shfl_xor_sync(0xffffffffu, mx0, 2));
        mx1 = fmaxf(mx1, __shfl_xor_sync(0xffffffffu, mx1, 1));
        mx1 = fmaxf(mx1, __shfl_xor_sync(0xffffffffu, mx1, 2));

        float mn0 = fmaxf(m0r, mx0), mn1 = fmaxf(m1r, mx1);
        float corr0 = __expf(m0r - mn0), corr1 = __expf(m1r - mn1);
        m0r = mn0; m1r = mn1;

        float ls0 = 0.f, ls1 = 0.f;
        #pragma unroll
        for (int nt = 0; nt < 8; nt++) {
            s[nt][0] = __expf(s[nt][0] - mn0);
            s[nt][1] = __expf(s[nt][1] - mn0);
            s[nt][2] = __expf(s[nt][2] - mn1);
            s[nt][3] = __expf(s[nt][3] - mn1);
            ls0 += s[nt][0] + s[nt][1];
            ls1 += s[nt][2] + s[nt][3];
        }
        ls0 += __shfl_xor_sync(0xffffffffu, ls0, 1);
        ls0 += __shfl_xor_sync(0xffffffffu, ls0, 2);
        ls1 += __shfl_xor_sync(0xffffffffu, ls1, 1);
        ls1 += __shfl_xor_sync(0xffffffffu, ls1, 2);
        l0r = l0r * corr0 + ls0;
        l1r = l1r * corr1 + ls1;

        #pragma unroll
        for (int dt = 0; dt < 8; dt++) {
            o[dt][0] *= corr0; o[dt][1] *= corr0;
            o[dt][2] *= corr1; o[dt][3] *= corr1;
        }

        // O += P V  (C-frag of S is exactly the A-frag of P)
        #pragma unroll
        for (int t = 0; t < 4; t++) {
            uint2 p0 = pack2(s[2 * t    ][0], s[2 * t    ][1]);
            uint2 p1 = pack2(s[2 * t    ][2], s[2 * t    ][3]);
            uint2 p2 = pack2(s[2 * t + 1][0], s[2 * t + 1][1]);
            uint2 p3 = pack2(s[2 * t + 1][2], s[2 * t + 1][3]);
            #pragma unroll
            for (int dt = 0; dt < 8; dt++) {
                uint2 b0 = Vs[(t * 8 + c    ) * 72 + dt * 8 + g];
                uint2 b1 = Vs[(t * 8 + c + 4) * 72 + dt * 8 + g];
                mma16(o[dt], p0.x, p1.x, p2.x, p3.x, b0.x, b1.x);
                mma16(o[dt], p0.x, p1.x, p2.x, p3.x, b0.y, b1.y);
                mma16(o[dt], p0.y, p1.y, p2.y, p3.y, b0.x, b1.x);
            }
        }
        __syncthreads();
    }

    // Normalize + pack pairs + scatter to [k2][m]
    int b = bh >> 4, h = bh & 15;
    float inv0 = 1.f / l0r, inv1 = 1.f / l1r;
    size_t mbase = (size_t)b * SS + qrow0;
    #pragma unroll
    for (int dt = 0; dt < 8; dt++) {
        size_t k2g = h * 32 + dt * 4 + c;
        g_aop[k2g * MTOT + mbase + g    ] = pack2(o[dt][0] * inv0, o[dt][1] * inv0);
        g_aop[k2g * MTOT + mbase + g + 8] = pack2(o[dt][2] * inv1, o[dt][3] * inv1);
    }
}

// ---------------------------------------------------------------------------
// Kernel 3: out = attn @ out_w^T + out_b (M=4096, N=1024, K=1024), bf16x3,
// cp.async 2-stage double buffer.
// ---------------------------------------------------------------------------
__global__ __launch_bounds__(256) void out_gemm_kernel(
    const float* __restrict__ bias, float* __restrict__ out)
{
    extern __shared__ __align__(16) uint2 dsm[];
    uint2* As = dsm;
    uint2* Bs = dsm + 2 * GEMM_STG;

    const int tid  = threadIdx.x;
    const int lane = tid & 31, warp = tid >> 5;
    const int g = lane >> 2, c = lane & 3;
    const int wm = warp >> 2, wn = warp & 3;
    const int m0 = blockIdx.y * 128, n0 = blockIdx.x * 128;

    float acc[4][4][4];
    #pragma unroll
    for (int mt = 0; mt < 4; mt++)
        #pragma unroll
        for (int nt = 0; nt < 4; nt++)
            #pragma unroll
            for (int i = 0; i < 4; i++) acc[mt][nt][i] = 0.f;

    auto copy_tile = [&](int stage, int k0) {
        uint2* Ad = As + stage * GEMM_STG;
        uint2* Bd = Bs + stage * GEMM_STG;
        #pragma unroll
        for (int l = 0; l < 4; l++) {
            int idx = l * 256 + tid;
            int k2l = idx >> 6, m4 = idx & 63;
            cp16(&Ad[k2l * 136 + m4 * 2],
                 g_aop + (size_t)(k0 + k2l) * MTOT + m0 + m4 * 2);
            cp16(&Bd[k2l * 136 + m4 * 2],
                 g_wop + (size_t)(k0 + k2l) * DM + n0 + m4 * 2);
        }
    };

    copy_tile(0, 0);
    CP_COMMIT();

    for (int it = 0; it < 32; it++) {
        if (it + 1 < 32) copy_tile((it + 1) & 1, (it + 1) * 16);
        CP_COMMIT();
        CP_WAIT1();
        __syncthreads();

        const uint2* Ac = As + (it & 1) * GEMM_STG;
        const uint2* Bc = Bs + (it & 1) * GEMM_STG;

        #pragma unroll
        for (int ks = 0; ks < 16; ks += 8) {
            uint2 a[4][4];
            #pragma unroll
            for (int mt = 0; mt < 4; mt++) {
                int mb = wm * 64 + mt * 16 + g;
                a[mt][0] = Ac[(ks + c    ) * 136 + mb];
                a[mt][1] = Ac[(ks + c    ) * 136 + mb + 8];
                a[mt][2] = Ac[(ks + c + 4) * 136 + mb];
                a[mt][3] = Ac[(ks + c + 4) * 136 + mb + 8];
            }
            #pragma unroll
            for (int nt = 0; nt < 4; nt++) {
                int nb = wn * 32 + nt * 8 + g;
                uint2 b0 = Bc[(ks + c    ) * 136 + nb];
                uint2 b1 = Bc[(ks + c + 4) * 136 + nb];
                #pragma unroll
                for (int mt = 0; mt < 4; mt++) {
                    mma16(acc[mt][nt], a[mt][0].x, a[mt][1].x, a[mt][2].x, a[mt][3].x, b0.x, b1.x);
                    mma16(acc[mt][nt], a[mt][0].x, a[mt][1].x, a[mt][2].x, a[mt][3].x, b0.y, b1.y);
                    mma16(acc[mt][nt], a[mt][0].y, a[mt][1].y, a[mt][2].y, a[mt][3].y, b0.x, b1.x);
                }
            }
        }
        __syncthreads();
    }

    #pragma unroll
    for (int mt = 0; mt < 4; mt++)
        #pragma unroll
        for (int i2 = 0; i2 < 2; i2++) {
            int m = m0 + wm * 64 + mt * 16 + g + i2 * 8;
            #pragma unroll
            for (int nt = 0; nt < 4; nt++) {
                int n = n0 + wn * 32 + nt * 8 + 2 * c;
                float2 r = make_float2(acc[mt][nt][i2 * 2 + 0] + bias[n],
                                       acc[mt][nt][i2 * 2 + 1] + bias[n + 1]);
                *(float2*)(out + (size_t)m * DM + n) = r;
            }
        }
}

// ---------------------------------------------------------------------------
extern "C" void kernel_launch(void* const* d_in, const int* in_sizes, int n_in,
                              void* d_out, int out_size)
{
    const float* x      = (const float*)d_in[0];
    const float* qkv_w  = (const float*)d_in[1];
    const float* qkv_b  = (const float*)d_in[2];
    const float* out_w  = (const float*)d_in[3];
    const float* out_b  = (const float*)d_in[4];
    const float* akmin  = (const float*)d_in[5];
    const float* akmax  = (const float*)d_in[6];
    const float* avmin  = (const float*)d_in[7];
    const float* avmax  = (const float*)d_in[8];
    float* out = (float*)d_out;

    const int gemm_smem = 2 * 2 * GEMM_STG * (int)sizeof(uint2);  // 69632
    const int att_smem  = 2 * ATT_STG * (int)sizeof(uint2);       // 73728
    cudaFuncSetAttribute(qkv_gemm_kernel,
                         cudaFuncAttributeMaxDynamicSharedMemorySize, gemm_smem);
    cudaFuncSetAttribute(out_gemm_kernel,
                         cudaFuncAttributeMaxDynamicSharedMemorySize, gemm_smem);
    cudaFuncSetAttribute(attn_kernel,
                         cudaFuncAttributeMaxDynamicSharedMemorySize, att_smem);

    conv_t_kernel<<<dim3(MTOT / 32, 16), 256>>>(x,     0, MTOT);
    conv_t_kernel<<<dim3(NQKV / 32, 16), 256>>>(qkv_w, 1, NQKV);
    conv_t_kernel<<<dim3(DM   / 32, 16), 256>>>(out_w, 2, DM);

    qkv_gemm_kernel<<<dim3(NQKV / 128, MTOT / 128), 256, gemm_smem>>>(
        qkv_b, akmin, akmax, avmin, avmax);

    conv_v_kernel<<<8192, 256>>>();

    attn_kernel<<<dim3(SS / 128, BB * HH), 256, att_smem>>>();

    out_gemm_kernel<<<dim3(DM / 128, MTOT / 128), 256, gemm_smem>>>(out_b, out);
}